// round 2
// baseline (speedup 1.0000x reference)
#include <cuda_runtime.h>
#include <stdint.h>

#define BB 4
#define SS 2048
#define DD 1024
#define EE 64
#define CC 64
#define ROWS (BB*SS)          // 8192
#define NOISE_SCALE (1.0f/64.0f)
#define HALF ((size_t)BB*SS*EE*CC)   // 33,554,432 elements per output array

// Scratch: gates transposed [b][e][s]  (2 MB)
__device__ float g_gatesT[(size_t)BB*EE*SS];

__device__ __forceinline__ float2 ffma2(float2 a, float2 b, float2 c) {
    unsigned long long au = *reinterpret_cast<unsigned long long*>(&a);
    unsigned long long bu = *reinterpret_cast<unsigned long long*>(&b);
    unsigned long long cu = *reinterpret_cast<unsigned long long*>(&c);
    unsigned long long du;
    asm("fma.rn.f32x2 %0, %1, %2, %3;" : "=l"(du) : "l"(au), "l"(bu), "l"(cu));
    return *reinterpret_cast<float2*>(&du);
}

// ---------------------------------------------------------------------------
// Kernel 1: logits GEMM (packed f32x2 FMA) + noise + softmax -> gatesT[b][e][s]
// Also zeroes the entire mask output array (DRAM hidden under compute).
// Block: 256 threads, 64 rows x 64 experts tile. Grid: 128 blocks.
// ---------------------------------------------------------------------------
__global__ __launch_bounds__(256, 1)
void gemm_softmax_kernel(const float* __restrict__ X,
                         const float* __restrict__ W,
                         const float* __restrict__ noise,
                         float* __restrict__ mask_out)
{
    __shared__ float2 As2[64][64];   // [row][k], value splat into both lanes (32KB)
    __shared__ float  Ws[64][64];    // [k][expert] (16KB); reused for logits in epilogue

    const int tid  = threadIdx.x;
    const int tx   = tid & 15;       // expert group (4 experts)
    const int ty   = tid >> 4;       // row group (4 rows)
    const int row0 = blockIdx.x * 64;

    // Zero this block's share of the mask array: 65536 float4 per block.
    {
        const float4 z = make_float4(0.f, 0.f, 0.f, 0.f);
        float4* mp = reinterpret_cast<float4*>(mask_out) + (size_t)blockIdx.x * 65536;
        for (int i = tid; i < 65536; i += 256) mp[i] = z;
    }

    float2 acc[4][2];
#pragma unroll
    for (int i = 0; i < 4; i++) {
        acc[i][0] = make_float2(0.f, 0.f);
        acc[i][1] = make_float2(0.f, 0.f);
    }

    for (int k0 = 0; k0 < DD; k0 += 64) {
        // A tile: 64 rows x 64 k, splat-stored as float2
#pragma unroll
        for (int p = 0; p < 4; p++) {
            int r  = (tid >> 4) + p * 16;
            int kv = (tid & 15) * 4;
            float4 v = *(const float4*)&X[(size_t)(row0 + r) * DD + k0 + kv];
            As2[r][kv + 0] = make_float2(v.x, v.x);
            As2[r][kv + 1] = make_float2(v.y, v.y);
            As2[r][kv + 2] = make_float2(v.z, v.z);
            As2[r][kv + 3] = make_float2(v.w, v.w);
        }
        // W tile: 64 k x 64 experts
#pragma unroll
        for (int p = 0; p < 4; p++) {
            int kk = (tid >> 4) + p * 16;
            int ev = (tid & 15) * 4;
            *(float4*)&Ws[kk][ev] = *(const float4*)&W[(size_t)(k0 + kk) * EE + ev];
        }
        __syncthreads();

#pragma unroll
        for (int kk = 0; kk < 64; kk++) {
            float4 bv = *(const float4*)&Ws[kk][tx * 4];
            float2 b01 = make_float2(bv.x, bv.y);
            float2 b23 = make_float2(bv.z, bv.w);
#pragma unroll
            for (int i = 0; i < 4; i++) {
                float2 a = As2[ty * 4 + i][kk];
                acc[i][0] = ffma2(a, b01, acc[i][0]);
                acc[i][1] = ffma2(a, b23, acc[i][1]);
            }
        }
        __syncthreads();
    }

    // Epilogue: logits + noise into Ws (reused as [row][expert])
#pragma unroll
    for (int i = 0; i < 4; i++) {
        int r   = ty * 4 + i;
        int row = row0 + r;
        float n0 = noise[(size_t)row * EE + tx * 4 + 0] * NOISE_SCALE;
        float n1 = noise[(size_t)row * EE + tx * 4 + 1] * NOISE_SCALE;
        float n2 = noise[(size_t)row * EE + tx * 4 + 2] * NOISE_SCALE;
        float n3 = noise[(size_t)row * EE + tx * 4 + 3] * NOISE_SCALE;
        Ws[r][tx * 4 + 0] = acc[i][0].x + n0;
        Ws[r][tx * 4 + 1] = acc[i][0].y + n1;
        Ws[r][tx * 4 + 2] = acc[i][1].x + n2;
        Ws[r][tx * 4 + 3] = acc[i][1].y + n3;
    }
    __syncthreads();

    // Softmax per row, write transposed gates.
    if (tid < 64) {
        int r   = tid;
        int row = row0 + r;
        int b   = row / SS;
        int s   = row % SS;
        float m = -1e30f;
#pragma unroll
        for (int e = 0; e < EE; e++) m = fmaxf(m, Ws[r][e]);
        float sum = 0.0f;
        float tv[EE];
#pragma unroll
        for (int e = 0; e < EE; e++) {
            float t = expf(Ws[r][e] - m);
            tv[e] = t;
            sum += t;
        }
        float inv = 1.0f / sum;
#pragma unroll
        for (int e = 0; e < EE; e++) {
            g_gatesT[((size_t)b * EE + e) * SS + s] = tv[e] * inv;
        }
    }
}

// ---------------------------------------------------------------------------
// Kernel 2: per-(b,e) exact top-64 via MSD radix select (u64 keys, distinct)
// then a 256-wide bitonic sort of the candidate set for exact rank order.
// Also zeroes its own combine slice [b][*][e][*].
// Grid: 256 blocks (b*64+e), 512 threads.
// ---------------------------------------------------------------------------
__global__ __launch_bounds__(512, 1)
void topk_kernel(float* __restrict__ mask_out,
                 float* __restrict__ comb_out)
{
    __shared__ unsigned long long keys[SS];
    __shared__ unsigned long long cand[256];
    __shared__ int hist[256];
    __shared__ unsigned long long s_prefix, s_thresh;
    __shared__ int s_need, s_done, s_cnt;

    const int tid = threadIdx.x;
    const int b = blockIdx.x >> 6;
    const int e = blockIdx.x & 63;

    // Zero this block's combine slice: rows s=0..2047, 64 floats each.
    {
        const float4 z = make_float4(0.f, 0.f, 0.f, 0.f);
        float4* base = reinterpret_cast<float4*>(comb_out + ((size_t)b * SS) * EE * CC + (size_t)e * CC);
        const int part = tid & 3;                // 4 threads per row
        for (int s = tid >> 2; s < SS; s += 128) {
            float4* p = base + (size_t)s * (EE * CC / 4) + part * 4;
            p[0] = z; p[1] = z; p[2] = z; p[3] = z;
        }
    }

    // Build keys: (gate_bits << 32) | ~idx  -> desc order = value desc, idx asc
    const float* col = &g_gatesT[((size_t)b * EE + e) * SS];
    for (int i = tid; i < SS; i += 512) {
        unsigned int fb = __float_as_uint(col[i]);   // softmax gates > 0
        keys[i] = ((unsigned long long)fb << 32) | (unsigned int)(~i);
    }
    if (tid == 0) { s_done = 0; s_need = CC; s_prefix = 0ULL; }
    __syncthreads();

    // MSD radix select, 8-bit digits. Exits when candidate set <= 256.
    for (int shift = 56; shift >= 0; shift -= 8) {
        if (s_done) break;
        if (tid < 256) hist[tid] = 0;
        __syncthreads();
        unsigned long long pf = s_prefix;
        for (int i = tid; i < SS; i += 512) {
            unsigned long long k = keys[i];
            bool active = (shift == 56) || ((k >> (shift + 8)) == pf);
            if (active) atomicAdd(&hist[(int)((k >> shift) & 255)], 1);
        }
        __syncthreads();
        if (tid == 0) {
            int need = s_need, c = 0, sel = 0;
            for (int d = 255; d >= 0; d--) {
                c += hist[d];
                if (c >= need) { sel = d; break; }
            }
            int above = c - hist[sel];
            int got = (CC - s_need) + c;            // global count of keys >= boundary
            unsigned long long np = (s_prefix << 8) | (unsigned long long)sel;
            if (got <= 256 || shift == 0) {
                s_thresh = np << shift;
                s_done = 1;
            } else {
                s_need = need - above;
                s_prefix = np;
            }
        }
        __syncthreads();
    }

    // Collect candidates (>= threshold), pad to 256 with 0.
    if (tid < 256) cand[tid] = 0ULL;
    if (tid == 0) s_cnt = 0;
    __syncthreads();
    {
        unsigned long long T = s_thresh;
        for (int i = tid; i < SS; i += 512) {
            unsigned long long k = keys[i];
            if (k >= T) { int p = atomicAdd(&s_cnt, 1); cand[p] = k; }
        }
    }
    __syncthreads();

    // Bitonic sort 256 keys descending (exact rank order for the top 64).
    for (int k2 = 2; k2 <= 256; k2 <<= 1) {
        for (int j = k2 >> 1; j > 0; j >>= 1) {
            if (tid < 128) {
                int i   = ((tid & ~(j - 1)) << 1) | (tid & (j - 1));
                int ixj = i | j;
                bool desc = ((i & k2) == 0);
                unsigned long long a = cand[i];
                unsigned long long c = cand[ixj];
                if ((a < c) == desc) { cand[i] = c; cand[ixj] = a; }
            }
            __syncthreads();
        }
    }

    // Scatter top-64 (rank = c)
    if (tid < CC) {
        unsigned long long k = cand[tid];
        int   s = (int)(~(unsigned int)k);
        float v = __uint_as_float((unsigned int)(k >> 32));
        size_t idx = ((((size_t)b * SS + s) * EE + e) << 6) + tid;
        mask_out[idx] = 1.0f;
        comb_out[idx] = v;
    }
}

// ---------------------------------------------------------------------------
extern "C" void kernel_launch(void* const* d_in, const int* in_sizes, int n_in,
                              void* d_out, int out_size)
{
    const float* X     = (const float*)d_in[0];   // [B,S,D]
    const float* W     = (const float*)d_in[1];   // [D,E]
    const float* noise = (const float*)d_in[2];   // [B,S,E]

    float* out = (float*)d_out;

    gemm_softmax_kernel<<<ROWS / 64, 256>>>(X, W, noise, out);
    topk_kernel<<<BB * EE, 512>>>(out, out + HALF);
}

// round 3
// speedup vs baseline: 1.2702x; 1.2702x over previous
#include <cuda_runtime.h>
#include <stdint.h>

#define BB 4
#define SS 2048
#define DD 1024
#define EE 64
#define CC 64
#define ROWS (BB*SS)          // 8192
#define NOISE_SCALE (1.0f/64.0f)
#define HALF ((size_t)BB*SS*EE*CC)      // elements per output array
#define TOTAL_F4 ((2*HALF)/4)           // float4 count of full output (16,777,216)

// Scratch: gates transposed [b][e][s]  (2 MB)
__device__ float g_gatesT[(size_t)BB*EE*SS];

// ---------------------------------------------------------------------------
// Zero kernel: pure coalesced fill of the whole 268MB output (runs on a forked
// stream, concurrent with the GEMM which doesn't touch d_out).
// ---------------------------------------------------------------------------
__global__ __launch_bounds__(256, 8)
void zero_kernel(float4* __restrict__ out)
{
    const float4 z = make_float4(0.f, 0.f, 0.f, 0.f);
    size_t stride = (size_t)gridDim.x * blockDim.x;
    for (size_t i = (size_t)blockIdx.x * blockDim.x + threadIdx.x; i < TOTAL_F4; i += stride)
        out[i] = z;
}

// ---------------------------------------------------------------------------
// Kernel 1: logits GEMM (fp32 FMA, 2-k inner step) + noise + softmax
// -> gatesT[b][e][s].  Block: 256 threads, 64 rows x 64 experts. Grid: 128.
// ---------------------------------------------------------------------------
__global__ __launch_bounds__(256, 1)
void gemm_softmax_kernel(const float* __restrict__ X,
                         const float* __restrict__ W,
                         const float* __restrict__ noise)
{
    __shared__ float As[64][66];   // [row][k], 8B-aligned row stride
    __shared__ float Ws[64][64];   // [k][expert]; reused for logits in epilogue

    const int tid  = threadIdx.x;
    const int tx   = tid & 15;     // expert group (4 experts)
    const int ty   = tid >> 4;     // row group (4 rows)
    const int row0 = blockIdx.x * 64;

    float acc[4][4];
#pragma unroll
    for (int i = 0; i < 4; i++)
#pragma unroll
        for (int j = 0; j < 4; j++) acc[i][j] = 0.0f;

    for (int k0 = 0; k0 < DD; k0 += 64) {
#pragma unroll
        for (int p = 0; p < 4; p++) {
            int r  = (tid >> 4) + p * 16;
            int kv = (tid & 15) * 4;
            float4 v = *(const float4*)&X[(size_t)(row0 + r) * DD + k0 + kv];
            As[r][kv + 0] = v.x;
            As[r][kv + 1] = v.y;
            As[r][kv + 2] = v.z;
            As[r][kv + 3] = v.w;
        }
#pragma unroll
        for (int p = 0; p < 4; p++) {
            int kk = (tid >> 4) + p * 16;
            int ev = (tid & 15) * 4;
            *(float4*)&Ws[kk][ev] = *(const float4*)&W[(size_t)(k0 + kk) * EE + ev];
        }
        __syncthreads();

#pragma unroll
        for (int kk = 0; kk < 64; kk += 2) {
            float4 b0 = *(const float4*)&Ws[kk + 0][tx * 4];
            float4 b1 = *(const float4*)&Ws[kk + 1][tx * 4];
#pragma unroll
            for (int i = 0; i < 4; i++) {
                float2 a = *(const float2*)&As[ty * 4 + i][kk];
                acc[i][0] += a.x * b0.x; acc[i][1] += a.x * b0.y;
                acc[i][2] += a.x * b0.z; acc[i][3] += a.x * b0.w;
                acc[i][0] += a.y * b1.x; acc[i][1] += a.y * b1.y;
                acc[i][2] += a.y * b1.z; acc[i][3] += a.y * b1.w;
            }
        }
        __syncthreads();
    }

    // Epilogue: logits + noise into Ws (reused as [row][expert])
#pragma unroll
    for (int i = 0; i < 4; i++) {
        int r   = ty * 4 + i;
        int row = row0 + r;
#pragma unroll
        for (int j = 0; j < 4; j++) {
            int e = tx * 4 + j;
            Ws[r][e] = acc[i][j] + noise[(size_t)row * EE + e] * NOISE_SCALE;
        }
    }
    __syncthreads();

    // Softmax per row (threads 0..63), write transposed gates.
    if (tid < 64) {
        int r   = tid;
        int row = row0 + r;
        int b   = row / SS;
        int s   = row % SS;
        float m = -1e30f;
#pragma unroll
        for (int e = 0; e < EE; e++) m = fmaxf(m, Ws[r][e]);
        float sum = 0.0f;
#pragma unroll
        for (int e = 0; e < EE; e++) {
            float t = expf(Ws[r][e] - m);
            Ws[r][e] = t;
            sum += t;
        }
        float inv = 1.0f / sum;
#pragma unroll
        for (int e = 0; e < EE; e++) {
            g_gatesT[((size_t)b * EE + e) * SS + s] = Ws[r][e] * inv;
        }
    }
}

// ---------------------------------------------------------------------------
// Kernel 2: per-(b,e) exact top-64 via MSD radix select on u64 keys
// (gate_bits<<32)|~idx (distinct), then bitonic sort of <=512 candidates for
// exact rank order, then scatter. Grid: 256 blocks, 512 threads.
// ---------------------------------------------------------------------------
__global__ __launch_bounds__(512, 2)
void topk_kernel(float* __restrict__ mask_out,
                 float* __restrict__ comb_out)
{
    __shared__ unsigned long long keys[SS];
    __shared__ unsigned long long cand[512];
    __shared__ int hist[256];
    __shared__ unsigned long long s_prefix, s_thresh;
    __shared__ int s_need, s_done, s_cnt;

    const int tid = threadIdx.x;
    const int b = blockIdx.x >> 6;
    const int e = blockIdx.x & 63;

    const float* col = &g_gatesT[((size_t)b * EE + e) * SS];
    for (int i = tid; i < SS; i += 512) {
        unsigned int fb = __float_as_uint(col[i]);   // softmax gates >= 0
        keys[i] = ((unsigned long long)fb << 32) | (unsigned int)(~i);
    }
    if (tid == 0) { s_done = 0; s_need = CC; s_prefix = 0ULL; }
    __syncthreads();

    // MSD radix select, 8-bit digits. Exits when candidate set <= 512.
    for (int shift = 56; shift >= 0; shift -= 8) {
        if (s_done) break;
        if (tid < 256) hist[tid] = 0;
        __syncthreads();
        unsigned long long pf = s_prefix;
        for (int i = tid; i < SS; i += 512) {
            unsigned long long k = keys[i];
            bool active = (shift == 56) || ((k >> (shift + 8)) == pf);
            if (active) atomicAdd(&hist[(int)((k >> shift) & 255)], 1);
        }
        __syncthreads();
        if (tid == 0) {
            int need = s_need, c = 0, sel = 0;
            for (int d = 255; d >= 0; d--) {
                c += hist[d];
                if (c >= need) { sel = d; break; }
            }
            int above = c - hist[sel];
            int got = (CC - s_need) + c;            // keys >= boundary, globally
            unsigned long long np = (s_prefix << 8) | (unsigned long long)sel;
            if (got <= 512 || shift == 0) {
                s_thresh = np << shift;             // keys >= thresh: <= 63+256 <= 512 worst case
                s_done = 1;
            } else {
                s_need = need - above;
                s_prefix = np;
            }
        }
        __syncthreads();
    }

    // Collect candidates (>= threshold), pad to 512 with 0 (real keys > 0).
    if (tid < 512) cand[tid] = 0ULL;
    if (tid == 0) s_cnt = 0;
    __syncthreads();
    {
        unsigned long long T = s_thresh;
        for (int i = tid; i < SS; i += 512) {
            unsigned long long k = keys[i];
            if (k >= T) { int p = atomicAdd(&s_cnt, 1); if (p < 512) cand[p] = k; }
        }
    }
    __syncthreads();

    // Bitonic sort 512 keys descending (exact ranks for the top 64).
    for (int k2 = 2; k2 <= 512; k2 <<= 1) {
        for (int j = k2 >> 1; j > 0; j >>= 1) {
            if (tid < 256) {
                int i   = ((tid & ~(j - 1)) << 1) | (tid & (j - 1));
                int ixj = i | j;
                bool desc = ((i & k2) == 0);
                unsigned long long a = cand[i];
                unsigned long long c = cand[ixj];
                if ((a < c) == desc) { cand[i] = c; cand[ixj] = a; }
            }
            __syncthreads();
        }
    }

    // Scatter top-64 (rank = c)
    if (tid < CC) {
        unsigned long long k = cand[tid];
        int   s = (int)(~(unsigned int)k);
        float v = __uint_as_float((unsigned int)(k >> 32));
        size_t idx = ((((size_t)b * SS + s) * EE + e) << 6) + tid;
        mask_out[idx] = 1.0f;
        comb_out[idx] = v;
    }
}

// ---------------------------------------------------------------------------
// Launch: fork the 268MB zero-fill onto a side stream so it runs concurrently
// with the GEMM (which doesn't touch d_out), join, then select+scatter.
// Statics are created on the (uncaptured) correctness call and reused; the
// fork/join event pattern is capturable and produces the same graph each call.
// ---------------------------------------------------------------------------
static cudaStream_t g_s2;
static cudaEvent_t  g_evFork, g_evJoin;
static bool         g_init = false;

extern "C" void kernel_launch(void* const* d_in, const int* in_sizes, int n_in,
                              void* d_out, int out_size)
{
    const float* X     = (const float*)d_in[0];   // [B,S,D]
    const float* W     = (const float*)d_in[1];   // [D,E]
    const float* noise = (const float*)d_in[2];   // [B,S,E]
    float* out = (float*)d_out;

    if (!g_init) {
        cudaStreamCreateWithFlags(&g_s2, cudaStreamNonBlocking);
        cudaEventCreateWithFlags(&g_evFork, cudaEventDisableTiming);
        cudaEventCreateWithFlags(&g_evJoin, cudaEventDisableTiming);
        g_init = true;
    }

    // Fork: zero-fill on side stream, concurrent with GEMM on main stream.
    cudaEventRecord(g_evFork, 0);
    cudaStreamWaitEvent(g_s2, g_evFork, 0);
    zero_kernel<<<2048, 256, 0, g_s2>>>((float4*)out);

    gemm_softmax_kernel<<<ROWS / 64, 256>>>(X, W, noise);

    // Join: topk needs both the gates and the zeroed output.
    cudaEventRecord(g_evJoin, g_s2);
    cudaStreamWaitEvent(0, g_evJoin, 0);

    topk_kernel<<<BB * EE, 512>>>(out, out + HALF);
}